// round 1
// baseline (speedup 1.0000x reference)
#include <cuda_runtime.h>
#include <cuda_bf16.h>
#include <math.h>

// ---------------- problem constants ----------------
#define BB   8
#define HH   32
#define WW   32
#define DIM  768
#define NH   6
#define NP   4
#define DV   384        // NH * 64
#define DH   64
#define HID  192
#define LQ   5376       // 21 * 256
#define LIN  1024       // 32*32
#define NTOK (BB*LQ)    // 43008
#define NFEAT (BB*LIN)  // 8192

// ---------------- scratch (device globals, no allocation) ----------------
__device__ float g_v[NFEAT * DV];        // value tensor  (B,1024,384)
__device__ float g_attn[NTOK * DV];      // pre-W_out attention output
__device__ float g_h1[NTOK * HID];       // fc1 output
__device__ float g_h2[NTOK * HID];       // dwconv+gelu output
__device__ float g_mu_q[NTOK], g_rs_q[NTOK];
__device__ float g_mu_f[NFEAT], g_rs_f[NFEAT];
__device__ float g_mu_x[NTOK], g_rs_x[NTOK];

// ---------------- LayerNorm stats: one block per row of 768 ----------------
__global__ __launch_bounds__(256) void ln_stats(const float* __restrict__ X,
                                                float* __restrict__ mu,
                                                float* __restrict__ rs)
{
    int row = blockIdx.x;
    const float* x = X + (size_t)row * DIM;
    float s = 0.f, q = 0.f;
    for (int i = threadIdx.x; i < DIM; i += 256) {
        float v = x[i];
        s += v; q += v * v;
    }
    __shared__ float ss[256], sq[256];
    ss[threadIdx.x] = s; sq[threadIdx.x] = q;
    __syncthreads();
    for (int o = 128; o > 0; o >>= 1) {
        if (threadIdx.x < o) {
            ss[threadIdx.x] += ss[threadIdx.x + o];
            sq[threadIdx.x] += sq[threadIdx.x + o];
        }
        __syncthreads();
    }
    if (threadIdx.x == 0) {
        float mean = ss[0] * (1.f / DIM);
        float var  = sq[0] * (1.f / DIM) - mean * mean;
        mu[row] = mean;
        rs[row] = rsqrtf(var + 1e-6f);
    }
}

// ---------------- fp32 GEMM: C[M,N] = epi( LN?(A)[M,K] @ B[K,N] ) ----------
// BM=128, BN=64, BK=16, 256 threads, 8x4 microtile.
// LN : apply (a-mu)*rs*g[k]+b[k] on A load
// RES: add residual R[M,N]
// ACC: accumulate into existing C
template<bool LN, bool RES, bool ACC>
__global__ __launch_bounds__(256) void gemm128x64(
    const float* __restrict__ A,
    const float* __restrict__ mu, const float* __restrict__ rs,
    const float* __restrict__ lng, const float* __restrict__ lnb,
    const float* __restrict__ Bw, const float* __restrict__ bias,
    const float* __restrict__ R, float* __restrict__ C,
    int M, int N, int K)
{
    __shared__ float As[16][128];
    __shared__ float Bs[16][64];

    const int bm = blockIdx.y * 128;
    const int bn = blockIdx.x * 64;
    const int tid = threadIdx.x;
    const int tx = tid & 15;       // 0..15 -> 4 output cols
    const int ty = tid >> 4;       // 0..15 -> 8 output rows
    const int arow = tid >> 1;     // 0..127
    const int ak   = (tid & 1) * 8;
    const int bk   = tid >> 4;     // 0..15
    const int bn4  = (tid & 15) * 4;

    float acc[8][4];
    #pragma unroll
    for (int i = 0; i < 8; i++)
        #pragma unroll
        for (int j = 0; j < 4; j++) acc[i][j] = 0.f;

    float lmu = 0.f, lrs = 0.f;
    if (LN) { lmu = mu[bm + arow]; lrs = rs[bm + arow]; }

    for (int k0 = 0; k0 < K; k0 += 16) {
        // ---- load A tile (each thread: 8 consecutive k of one row) ----
        const float* ap = A + (size_t)(bm + arow) * K + k0 + ak;
        float4 a0 = *(const float4*)(ap);
        float4 a1 = *(const float4*)(ap + 4);
        if (LN) {
            float4 g0 = *(const float4*)(lng + k0 + ak);
            float4 g1 = *(const float4*)(lng + k0 + ak + 4);
            float4 e0 = *(const float4*)(lnb + k0 + ak);
            float4 e1 = *(const float4*)(lnb + k0 + ak + 4);
            a0.x = (a0.x - lmu) * lrs * g0.x + e0.x;
            a0.y = (a0.y - lmu) * lrs * g0.y + e0.y;
            a0.z = (a0.z - lmu) * lrs * g0.z + e0.z;
            a0.w = (a0.w - lmu) * lrs * g0.w + e0.w;
            a1.x = (a1.x - lmu) * lrs * g1.x + e1.x;
            a1.y = (a1.y - lmu) * lrs * g1.y + e1.y;
            a1.z = (a1.z - lmu) * lrs * g1.z + e1.z;
            a1.w = (a1.w - lmu) * lrs * g1.w + e1.w;
        }
        As[ak + 0][arow] = a0.x; As[ak + 1][arow] = a0.y;
        As[ak + 2][arow] = a0.z; As[ak + 3][arow] = a0.w;
        As[ak + 4][arow] = a1.x; As[ak + 5][arow] = a1.y;
        As[ak + 6][arow] = a1.z; As[ak + 7][arow] = a1.w;
        // ---- load B tile ----
        float4 bv = *(const float4*)(Bw + (size_t)(k0 + bk) * N + bn + bn4);
        *(float4*)&Bs[bk][bn4] = bv;
        __syncthreads();

        #pragma unroll
        for (int k = 0; k < 16; k++) {
            float4 b4  = *(const float4*)&Bs[k][tx * 4];
            float4 av0 = *(const float4*)&As[k][ty * 8];
            float4 av1 = *(const float4*)&As[k][ty * 8 + 4];
            float ar[8] = {av0.x, av0.y, av0.z, av0.w, av1.x, av1.y, av1.z, av1.w};
            float br[4] = {b4.x, b4.y, b4.z, b4.w};
            #pragma unroll
            for (int i = 0; i < 8; i++)
                #pragma unroll
                for (int j = 0; j < 4; j++)
                    acc[i][j] += ar[i] * br[j];
        }
        __syncthreads();
    }

    // ---- epilogue ----
    float4 bcol = *(const float4*)(bias + bn + tx * 4);
    #pragma unroll
    for (int i = 0; i < 8; i++) {
        int row = bm + ty * 8 + i;
        size_t off = (size_t)row * N + bn + tx * 4;
        float4 o;
        o.x = acc[i][0] + bcol.x;
        o.y = acc[i][1] + bcol.y;
        o.z = acc[i][2] + bcol.z;
        o.w = acc[i][3] + bcol.w;
        if (RES) {
            float4 rv = *(const float4*)&R[off];
            o.x += rv.x; o.y += rv.y; o.z += rv.z; o.w += rv.w;
        }
        if (ACC) {
            float4 cv = *(const float4*)&C[off];
            o.x += cv.x; o.y += cv.y; o.z += cv.z; o.w += cv.w;
        }
        *(float4*)&C[off] = o;
    }
}

// ---------------- fused deform-attn sampling kernel ----------------
// One block (384 threads) per query token:
//   LN(q) -> 48 offset + 24 attn logits -> softmax(4) -> bilinear gather
//   from g_v -> weighted sum -> g_attn[token][384]
__global__ __launch_bounds__(384) void sample_kernel(
    const float* __restrict__ query, const float* __restrict__ refp,
    const float* __restrict__ qn_g, const float* __restrict__ qn_b,
    const float* __restrict__ W_off, const float* __restrict__ b_off,
    const float* __restrict__ W_attn, const float* __restrict__ b_attn,
    const float* __restrict__ mu, const float* __restrict__ rs)
{
    __shared__ float qln[DIM];
    __shared__ float partial[288];
    __shared__ float oa[72];
    __shared__ float aw[24];
    __shared__ int   sidx[24][4];
    __shared__ float swt[24][4];

    const int t = blockIdx.x;         // global token
    const int b = t / LQ;
    const int tid = threadIdx.x;

    const float m = mu[t], r = rs[t];
    const float* qrow = query + (size_t)t * DIM;
    for (int i = tid; i < DIM; i += 384)
        qln[i] = (qrow[i] - m) * r * qn_g[i] + qn_b[i];
    __syncthreads();

    // --- 72 projections, split-K by 4 ---
    if (tid < 288) {
        int col = tid % 72, ks = tid / 72;
        const float* Wp; int ld, cc;
        if (col < 48) { Wp = W_off;  ld = 48; cc = col; }
        else          { Wp = W_attn; ld = 24; cc = col - 48; }
        float s = 0.f;
        int k0 = ks * 192;
        #pragma unroll 8
        for (int k = 0; k < 192; k++)
            s += qln[k0 + k] * Wp[(size_t)(k0 + k) * ld + cc];
        partial[tid] = s;
    }
    __syncthreads();
    if (tid < 72) {
        float s = partial[tid] + partial[tid + 72] + partial[tid + 144] + partial[tid + 216];
        s += (tid < 48) ? b_off[tid] : b_attn[tid - 48];
        oa[tid] = s;
    }
    __syncthreads();

    // --- softmax over 4 points per head ---
    if (tid < NH) {
        int h = tid;
        float v0 = oa[48 + h * 4 + 0], v1 = oa[48 + h * 4 + 1];
        float v2 = oa[48 + h * 4 + 2], v3 = oa[48 + h * 4 + 3];
        float mx = fmaxf(fmaxf(v0, v1), fmaxf(v2, v3));
        float e0 = expf(v0 - mx), e1 = expf(v1 - mx);
        float e2 = expf(v2 - mx), e3 = expf(v3 - mx);
        float inv = 1.f / (e0 + e1 + e2 + e3);
        aw[h * 4 + 0] = e0 * inv; aw[h * 4 + 1] = e1 * inv;
        aw[h * 4 + 2] = e2 * inv; aw[h * 4 + 3] = e3 * inv;
    }
    __syncthreads();

    // --- per (head, point): compute 4 corner indices + weights ---
    if (tid < 24) {
        int h = tid >> 2, p = tid & 3;
        float rx = refp[(size_t)t * 2 + 0];
        float ry = refp[(size_t)t * 2 + 1];
        float lx = rx + oa[h * 8 + p * 2 + 0] * (1.f / (float)WW);
        float ly = ry + oa[h * 8 + p * 2 + 1] * (1.f / (float)HH);
        float x = lx * (float)WW - 0.5f;
        float y = ly * (float)HH - 0.5f;
        float x0f = floorf(x), y0f = floorf(y);
        float wx = x - x0f, wy = y - y0f;
        int x0 = (int)x0f, y0 = (int)y0f;
        float a = aw[tid];
        #pragma unroll
        for (int c = 0; c < 4; c++) {
            int dx = c & 1, dy = c >> 1;
            int xi = x0 + dx, yi = y0 + dy;
            bool ok = (xi >= 0) && (xi < WW) && (yi >= 0) && (yi < HH);
            sidx[tid][c] = ok ? (yi * WW + xi) : -1;
            float wgt = (dx ? wx : 1.f - wx) * (dy ? wy : 1.f - wy);
            swt[tid][c] = ok ? wgt * a : 0.f;
        }
    }
    __syncthreads();

    // --- gather + weighted sum: one thread per output dim (384) ---
    {
        int d = tid;
        int h = d >> 6;
        float acc = 0.f;
        const float* vb = g_v + (size_t)b * LIN * DV;
        #pragma unroll
        for (int p = 0; p < 4; p++) {
            int hp = h * 4 + p;
            #pragma unroll
            for (int c = 0; c < 4; c++) {
                int idx = sidx[hp][c];
                float wv = swt[hp][c];
                if (idx >= 0) acc += wv * vb[(size_t)idx * DV + d];
            }
        }
        g_attn[(size_t)t * DV + d] = acc;
    }
}

// ---------------- depthwise 3x3 conv + exact GELU ----------------
__global__ __launch_bounds__(256) void dwconv_gelu(
    const float* __restrict__ hin, const float* __restrict__ dww,
    const float* __restrict__ dwb, float* __restrict__ hout)
{
    int gid = blockIdx.x * 256 + threadIdx.x;
    if (gid >= NTOK * HID) return;
    int ch = gid % HID;
    int t  = (gid / HID) % LQ;
    int b  = gid / (HID * LQ);

    int base, hh, ww;
    if (t < 4096)      { base = 0;    hh = 64; ww = 64; }
    else if (t < 5120) { base = 4096; hh = 32; ww = 32; }
    else               { base = 5120; hh = 16; ww = 16; }
    int tl = t - base;
    int rr = tl / ww, cc = tl % ww;

    const float* in = hin + ((size_t)b * LQ + base) * HID + ch;
    float acc = dwb[ch];
    #pragma unroll
    for (int ky = 0; ky < 3; ky++) {
        int y = rr + ky - 1;
        if (y < 0 || y >= hh) continue;
        #pragma unroll
        for (int kx = 0; kx < 3; kx++) {
            int x = cc + kx - 1;
            if (x < 0 || x >= ww) continue;
            acc += in[(size_t)(y * ww + x) * HID] * dww[(ky * 3 + kx) * HID + ch];
        }
    }
    // exact GELU: x * 0.5 * (1 + erf(x/sqrt(2)))
    hout[gid] = 0.5f * acc * (1.f + erff(acc * 0.70710678118654752440f));
}

// ---------------- host launcher ----------------
extern "C" void kernel_launch(void* const* d_in, const int* in_sizes, int n_in,
                              void* d_out, int out_size)
{
    const float* query  = (const float*)d_in[0];
    const float* refp   = (const float*)d_in[1];
    const float* feat   = (const float*)d_in[2];
    const float* qn_g   = (const float*)d_in[5];
    const float* qn_b   = (const float*)d_in[6];
    const float* fn_g   = (const float*)d_in[7];
    const float* fn_b   = (const float*)d_in[8];
    const float* W_off  = (const float*)d_in[9];
    const float* b_off  = (const float*)d_in[10];
    const float* W_attn = (const float*)d_in[11];
    const float* b_attn = (const float*)d_in[12];
    const float* W_val  = (const float*)d_in[13];
    const float* b_val  = (const float*)d_in[14];
    const float* W_out  = (const float*)d_in[15];
    const float* b_out  = (const float*)d_in[16];
    const float* ffn_g  = (const float*)d_in[17];
    const float* ffn_b  = (const float*)d_in[18];
    const float* fc1_w  = (const float*)d_in[19];
    const float* fc1_b  = (const float*)d_in[20];
    const float* dw_w   = (const float*)d_in[21];
    const float* dw_b   = (const float*)d_in[22];
    const float* fc2_w  = (const float*)d_in[23];
    const float* fc2_b  = (const float*)d_in[24];
    float* out = (float*)d_out;

    float *pv, *pattn, *ph1, *ph2;
    float *pmuq, *prsq, *pmuf, *prsf, *pmux, *prsx;
    cudaGetSymbolAddress((void**)&pv,    g_v);
    cudaGetSymbolAddress((void**)&pattn, g_attn);
    cudaGetSymbolAddress((void**)&ph1,   g_h1);
    cudaGetSymbolAddress((void**)&ph2,   g_h2);
    cudaGetSymbolAddress((void**)&pmuq,  g_mu_q);
    cudaGetSymbolAddress((void**)&prsq,  g_rs_q);
    cudaGetSymbolAddress((void**)&pmuf,  g_mu_f);
    cudaGetSymbolAddress((void**)&prsf,  g_rs_f);
    cudaGetSymbolAddress((void**)&pmux,  g_mu_x);
    cudaGetSymbolAddress((void**)&prsx,  g_rs_x);

    // 1) LN stats for query and feat
    ln_stats<<<NTOK, 256>>>(query, pmuq, prsq);
    ln_stats<<<NFEAT, 256>>>(feat, pmuf, prsf);

    // 2) v = LN(feat) @ W_val + b_val          (8192 x 384, K=768)
    gemm128x64<true, false, false><<<dim3(DV / 64, NFEAT / 128), 256>>>(
        feat, pmuf, prsf, fn_g, fn_b, W_val, b_val, nullptr, pv,
        NFEAT, DV, DIM);

    // 3) fused offsets/attn/softmax/bilinear   -> g_attn (43008 x 384)
    sample_kernel<<<NTOK, 384>>>(query, refp, qn_g, qn_b,
                                 W_off, b_off, W_attn, b_attn, pmuq, prsq);

    // 4) x = g_attn @ W_out + b_out + query    -> d_out (43008 x 768, K=384)
    gemm128x64<false, true, false><<<dim3(DIM / 64, NTOK / 128), 256>>>(
        pattn, nullptr, nullptr, nullptr, nullptr, W_out, b_out, query, out,
        NTOK, DIM, DV);

    // 5) LN stats for x
    ln_stats<<<NTOK, 256>>>(out, pmux, prsx);

    // 6) h1 = LN(x) @ fc1_w + fc1_b            (43008 x 192, K=768)
    gemm128x64<true, false, false><<<dim3(HID / 64, NTOK / 128), 256>>>(
        out, pmux, prsx, ffn_g, ffn_b, fc1_w, fc1_b, nullptr, ph1,
        NTOK, HID, DIM);

    // 7) depthwise 3x3 conv (per pyramid level) + exact GELU -> h2
    dwconv_gelu<<<(NTOK * HID) / 256, 256>>>(ph1, dw_w, dw_b, ph2);

    // 8) out += h2 @ fc2_w + fc2_b             (43008 x 768, K=192)
    gemm128x64<false, false, true><<<dim3(DIM / 64, NTOK / 128), 256>>>(
        ph2, nullptr, nullptr, nullptr, nullptr, fc2_w, fc2_b, nullptr, out,
        NTOK, DIM, HID);
}

// round 3
// speedup vs baseline: 3.1828x; 3.1828x over previous
#include <cuda_runtime.h>
#include <cuda_bf16.h>
#include <math.h>
#include <stdint.h>

// ---------------- problem constants ----------------
#define BB   8
#define HH   32
#define WW   32
#define DIM  768
#define NH   6
#define NP   4
#define DV   384
#define DH   64
#define HID  192
#define LQ   5376
#define LIN  1024
#define NTOK (BB*LQ)    // 43008
#define NFEAT (BB*LIN)  // 8192
#define OA_LD 96        // padded projection width (48 off + 24 logits + pad)

// ---------------- scratch (device globals) ----------------
__device__ float g_v[NFEAT * DV];
__device__ float g_oa[NTOK * OA_LD];
__device__ float g_h1[NTOK * HID];
__device__ __nv_bfloat16 g_lnq[NTOK * DIM];
__device__ __nv_bfloat16 g_lnf[NFEAT * DIM];
__device__ __nv_bfloat16 g_lnx[NTOK * DIM];
__device__ __nv_bfloat16 g_attnb[NTOK * DV];
__device__ __nv_bfloat16 g_h2b[NTOK * HID];
__device__ __nv_bfloat16 g_wval[DV * DIM];
__device__ __nv_bfloat16 g_wout[DIM * DV];
__device__ __nv_bfloat16 g_wproj[OA_LD * DIM];
__device__ __nv_bfloat16 g_wfc1[HID * DIM];
__device__ __nv_bfloat16 g_wfc2[DIM * HID];
__device__ float g_bproj[OA_LD];

// ---------------- PTX helpers (all sm_80+ portable) ----------------
__device__ __forceinline__ uint32_t smem_u32(const void* p) {
    uint32_t a;
    asm("{ .reg .u64 t; cvta.to.shared.u64 t, %1; cvt.u32.u64 %0, t; }" : "=r"(a) : "l"(p));
    return a;
}
__device__ __forceinline__ void cp16(uint32_t s, const void* g) {
    asm volatile("cp.async.cg.shared.global [%0], [%1], 16;" :: "r"(s), "l"(g));
}
#define CP_COMMIT() asm volatile("cp.async.commit_group;" ::: "memory")
#define CP_WAIT(n)  asm volatile("cp.async.wait_group %0;" :: "n"(n) : "memory")

__device__ __forceinline__ void ldmx4(uint32_t* r, uint32_t addr) {
    asm volatile("ldmatrix.sync.aligned.m8n8.x4.shared.b16 {%0,%1,%2,%3}, [%4];"
        : "=r"(r[0]), "=r"(r[1]), "=r"(r[2]), "=r"(r[3]) : "r"(addr));
}
__device__ __forceinline__ void mma16816(float* c, const uint32_t* a, const uint32_t* b) {
    asm volatile(
        "mma.sync.aligned.m16n8k16.row.col.f32.bf16.bf16.f32 "
        "{%0,%1,%2,%3}, {%4,%5,%6,%7}, {%8,%9}, {%0,%1,%2,%3};"
        : "+f"(c[0]), "+f"(c[1]), "+f"(c[2]), "+f"(c[3])
        : "r"(a[0]), "r"(a[1]), "r"(a[2]), "r"(a[3]), "r"(b[0]), "r"(b[1]));
}

// ---------------- fused LayerNorm + bf16 cast ----------------
__global__ __launch_bounds__(256) void ln_cast(const float* __restrict__ X,
                                               const float* __restrict__ g,
                                               const float* __restrict__ bta,
                                               __nv_bfloat16* __restrict__ Y)
{
    int row = blockIdx.x;
    const float* x = X + (size_t)row * DIM;
    float s = 0.f, q = 0.f;
    for (int i = threadIdx.x; i < DIM; i += 256) {
        float v = x[i];
        s += v; q += v * v;
    }
    __shared__ float ss[256], sq[256];
    ss[threadIdx.x] = s; sq[threadIdx.x] = q;
    __syncthreads();
    for (int o = 128; o > 0; o >>= 1) {
        if (threadIdx.x < o) {
            ss[threadIdx.x] += ss[threadIdx.x + o];
            sq[threadIdx.x] += sq[threadIdx.x + o];
        }
        __syncthreads();
    }
    __shared__ float s_m, s_r;
    if (threadIdx.x == 0) {
        float mean = ss[0] * (1.f / DIM);
        float var  = sq[0] * (1.f / DIM) - mean * mean;
        s_m = mean;
        s_r = rsqrtf(var + 1e-6f);
    }
    __syncthreads();
    float m = s_m, r = s_r;
    __nv_bfloat16* y = Y + (size_t)row * DIM;
    for (int i = threadIdx.x; i < DIM; i += 256)
        y[i] = __float2bfloat16((x[i] - m) * r * g[i] + bta[i]);
}

// ---------------- transpose-cast weight: Wt[n*K+k] = bf16(W[k*N+n]) -----
__global__ __launch_bounds__(256) void tcast(const float* __restrict__ W,
                                             __nv_bfloat16* __restrict__ Wt,
                                             int K, int N)
{
    int gid = blockIdx.x * 256 + threadIdx.x;
    if (gid >= K * N) return;
    int k = gid / N, n = gid % N;
    Wt[(size_t)n * K + k] = __float2bfloat16(W[gid]);
}

// ---------------- build padded projection weight/bias -------------------
__global__ __launch_bounds__(256) void build_proj(const float* __restrict__ Woff,
                                                  const float* __restrict__ Wattn,
                                                  const float* __restrict__ boff,
                                                  const float* __restrict__ battn,
                                                  __nv_bfloat16* __restrict__ Wt,
                                                  float* __restrict__ bc)
{
    int gid = blockIdx.x * 256 + threadIdx.x;
    if (gid < OA_LD * DIM) {
        int n = gid / DIM, k = gid % DIM;
        float v = 0.f;
        if (n < 48)      v = Woff[(size_t)k * 48 + n];
        else if (n < 72) v = Wattn[(size_t)k * 24 + (n - 48)];
        Wt[gid] = __float2bfloat16(v);
    }
    if (gid < OA_LD)
        bc[gid] = (gid < 48) ? boff[gid] : ((gid < 72) ? battn[gid - 48] : 0.f);
}

// ---------------- bf16 mma.sync GEMM: C[M,N] = A[M,K] @ Bt[N,K]^T + bias
// CTA tile 128x96, BK=32, 256 threads = 8 warps (4m x 2n), warp 32x48.
// Double-buffered cp.async; padded smem rows (40 halves) -> conflict-free
// ldmatrix (row stride 80B = 20 banks, gcd cycle covers 8 rows distinct).
#define BM 128
#define BN 96
#define APAD 40     // halves per A/B smem row

template<bool RES, bool ACC>
__global__ __launch_bounds__(256) void gemm_mma(
    const __nv_bfloat16* __restrict__ A,   // [M,K] row-major
    const __nv_bfloat16* __restrict__ Bt,  // [N,K] row-major (= B col-major)
    const float* __restrict__ bias,        // [N]
    const float* __restrict__ R,           // [M,N] residual (RES)
    float* __restrict__ C, int M, int N, int K)
{
    __shared__ __align__(16) __nv_bfloat16 sA[2][BM * APAD];
    __shared__ __align__(16) __nv_bfloat16 sB[2][BN * APAD];

    const int tid  = threadIdx.x;
    const int wid  = tid >> 5, lane = tid & 31;
    const int wm   = wid >> 1, wn = wid & 1;
    const int bm   = blockIdx.y * BM, bn = blockIdx.x * BN;

    float acc[2][6][4];
    #pragma unroll
    for (int i = 0; i < 2; i++)
        #pragma unroll
        for (int j = 0; j < 6; j++)
            #pragma unroll
            for (int v = 0; v < 4; v++) acc[i][j][v] = 0.f;

    const uint32_t uA = smem_u32(sA);
    const uint32_t uB = smem_u32(sB);

    // ldmatrix lane-address components
    const int a_r = wm * 32 + (lane & 15);       // + mt*16
    const int a_c = (lane >> 4) * 8;             // + kk*16
    const int b_r = wn * 48 + ((lane >> 4) & 1) * 8 + (lane & 7);  // + g*16
    const int b_c = ((lane >> 3) & 1) * 8;       // + kk*16

    // cp.async chunk coordinates
    const int ar0 = tid >> 2, ac0 = (tid & 3) * 8;             // A chunks 0-255
    const int ar1 = (tid + 256) >> 2;                          // A chunks 256-511
    const int br0 = tid >> 2, bc0 = (tid & 3) * 8;             // B chunks 0-255
    const int br1 = (tid + 256) >> 2;                          // B chunks 256-383 (tid<128)

    const int nk = K >> 5;

    // ---- prologue: stage 0 ----
    {
        const int k0 = 0;
        cp16(uA + (uint32_t)(ar0 * APAD + ac0) * 2, A + (size_t)(bm + ar0) * K + k0 + ac0);
        cp16(uA + (uint32_t)(ar1 * APAD + ac0) * 2, A + (size_t)(bm + ar1) * K + k0 + ac0);
        cp16(uB + (uint32_t)(br0 * APAD + bc0) * 2, Bt + (size_t)(bn + br0) * K + k0 + bc0);
        if (tid < 128)
            cp16(uB + (uint32_t)(br1 * APAD + bc0) * 2, Bt + (size_t)(bn + br1) * K + k0 + bc0);
        CP_COMMIT();
    }

    int buf = 0;
    for (int c = 0; c < nk; c++) {
        if (c + 1 < nk) {
            const int k0 = (c + 1) << 5;
            const int s = buf ^ 1;
            cp16(uA + (uint32_t)(s * BM * APAD + ar0 * APAD + ac0) * 2,
                 A + (size_t)(bm + ar0) * K + k0 + ac0);
            cp16(uA + (uint32_t)(s * BM * APAD + ar1 * APAD + ac0) * 2,
                 A + (size_t)(bm + ar1) * K + k0 + ac0);
            cp16(uB + (uint32_t)(s * BN * APAD + br0 * APAD + bc0) * 2,
                 Bt + (size_t)(bn + br0) * K + k0 + bc0);
            if (tid < 128)
                cp16(uB + (uint32_t)(s * BN * APAD + br1 * APAD + bc0) * 2,
                     Bt + (size_t)(bn + br1) * K + k0 + bc0);
            CP_COMMIT();
            CP_WAIT(1);
        } else {
            CP_WAIT(0);
        }
        __syncthreads();

        const uint32_t bA = uA + (uint32_t)(buf * BM * APAD) * 2;
        const uint32_t bB = uB + (uint32_t)(buf * BN * APAD) * 2;
        #pragma unroll
        for (int kk = 0; kk < 2; kk++) {
            uint32_t afr[2][4];
            #pragma unroll
            for (int mt = 0; mt < 2; mt++)
                ldmx4(afr[mt], bA + (uint32_t)((a_r + mt * 16) * APAD + kk * 16 + a_c) * 2);
            uint32_t bfr[6][2];
            #pragma unroll
            for (int g = 0; g < 3; g++) {
                uint32_t r[4];
                ldmx4(r, bB + (uint32_t)((b_r + g * 16) * APAD + kk * 16 + b_c) * 2);
                bfr[g * 2 + 0][0] = r[0]; bfr[g * 2 + 0][1] = r[1];
                bfr[g * 2 + 1][0] = r[2]; bfr[g * 2 + 1][1] = r[3];
            }
            #pragma unroll
            for (int mt = 0; mt < 2; mt++)
                #pragma unroll
                for (int nt = 0; nt < 6; nt++)
                    mma16816(acc[mt][nt], afr[mt], bfr[nt]);
        }
        __syncthreads();
        buf ^= 1;
    }

    // ---- epilogue ----
    const int er = bm + wm * 32 + (lane >> 2);
    const int ec = bn + wn * 48 + (lane & 3) * 2;
    #pragma unroll
    for (int mt = 0; mt < 2; mt++) {
        #pragma unroll
        for (int nt = 0; nt < 6; nt++) {
            const int row0 = er + mt * 16;
            const int col  = ec + nt * 8;
            float2 bv = *(const float2*)&bias[col];
            size_t off0 = (size_t)row0 * N + col;
            size_t off1 = off0 + (size_t)8 * N;
            float2 o0, o1;
            o0.x = acc[mt][nt][0] + bv.x; o0.y = acc[mt][nt][1] + bv.y;
            o1.x = acc[mt][nt][2] + bv.x; o1.y = acc[mt][nt][3] + bv.y;
            if (RES) {
                float2 r0 = *(const float2*)&R[off0];
                float2 r1 = *(const float2*)&R[off1];
                o0.x += r0.x; o0.y += r0.y; o1.x += r1.x; o1.y += r1.y;
            }
            if (ACC) {
                float2 c0 = *(const float2*)&C[off0];
                float2 c1 = *(const float2*)&C[off1];
                o0.x += c0.x; o0.y += c0.y; o1.x += c1.x; o1.y += c1.y;
            }
            *(float2*)&C[off0] = o0;
            *(float2*)&C[off1] = o1;
        }
    }
}

// ---------------- sampling: softmax + bilinear gather -------------------
// 192 threads: each handles 2 consecutive value dims (float2).
__global__ __launch_bounds__(192) void sample_kernel(
    const float* __restrict__ oa,       // [NTOK, 96]: 0-47 offsets, 48-71 logits
    const float* __restrict__ refp,
    __nv_bfloat16* __restrict__ attn_bf)
{
    __shared__ float aw[24];
    __shared__ int   sidx[24][4];
    __shared__ float swt[24][4];

    const int t = blockIdx.x;
    const int b = t / LQ;
    const int tid = threadIdx.x;
    const float* oarow = oa + (size_t)t * OA_LD;

    if (tid < NH) {
        int h = tid;
        float v0 = oarow[48 + h * 4 + 0], v1 = oarow[48 + h * 4 + 1];
        float v2 = oarow[48 + h * 4 + 2], v3 = oarow[48 + h * 4 + 3];
        float mx = fmaxf(fmaxf(v0, v1), fmaxf(v2, v3));
        float e0 = expf(v0 - mx), e1 = expf(v1 - mx);
        float e2 = expf(v2 - mx), e3 = expf(v3 - mx);
        float inv = 1.f / (e0 + e1 + e2 + e3);
        aw[h * 4 + 0] = e0 * inv; aw[h * 4 + 1] = e1 * inv;
        aw[h * 4 + 2] = e2 * inv; aw[h * 4 + 3] = e3 * inv;
    }
    __syncthreads();

    if (tid < 24) {
        int h = tid >> 2, p = tid & 3;
        float rx = refp[(size_t)t * 2 + 0];
        float ry = refp[(size_t)t * 2 + 1];
        float lx = rx + oarow[h * 8 + p * 2 + 0] * (1.f / (float)WW);
        float ly = ry + oarow[h * 8 + p * 2 + 1] * (1.f / (float)HH);
        float x = lx * (float)WW - 0.5f;
        float y = ly * (float)HH - 0.5f;
        float x0f = floorf(x), y0f = floorf(y);
        float wx = x - x0f, wy = y - y0f;
        int x0 = (int)x0f, y0 = (int)y0f;
        float a = aw[tid];
        #pragma unroll
        for (int c = 0; c < 4; c++) {
            int dx = c & 1, dy = c >> 1;
            int xi = x0 + dx, yi = y0 + dy;
            bool ok = (xi >= 0) && (xi < WW) && (yi >= 0) && (yi < HH);
            sidx[tid][c] = ok ? (yi * WW + xi) : -1;
            float wgt = (dx ? wx : 1.f - wx) * (dy ? wy : 1.f - wy);
            swt[tid][c] = ok ? wgt * a : 0.f;
        }
    }
    __syncthreads();

    {
        const int d = tid * 2;         // 0..382
        const int h = d >> 6;
        float ax = 0.f, ay = 0.f;
        const float* vb = g_v + (size_t)b * LIN * DV;
        #pragma unroll
        for (int p = 0; p < 4; p++) {
            int hp = h * 4 + p;
            #pragma unroll
            for (int c = 0; c < 4; c++) {
                int idx = sidx[hp][c];
                float wv = swt[hp][c];
                if (idx >= 0) {
                    float2 v = *(const float2*)&vb[(size_t)idx * DV + d];
                    ax += wv * v.x; ay += wv * v.y;
                }
            }
        }
        __nv_bfloat162 o;
        o.x = __float2bfloat16(ax); o.y = __float2bfloat16(ay);
        *(__nv_bfloat162*)&attn_bf[(size_t)t * DV + d] = o;
    }
}

// ---------------- depthwise 3x3 conv + exact GELU -> bf16 ---------------
__global__ __launch_bounds__(256) void dwconv_gelu(
    const float* __restrict__ hin, const float* __restrict__ dww,
    const float* __restrict__ dwb, __nv_bfloat16* __restrict__ hout)
{
    int gid = blockIdx.x * 256 + threadIdx.x;
    if (gid >= NTOK * HID) return;
    int ch = gid % HID;
    int t  = (gid / HID) % LQ;
    int b  = gid / (HID * LQ);

    int base, hh, ww;
    if (t < 4096)      { base = 0;    hh = 64; ww = 64; }
    else if (t < 5120) { base = 4096; hh = 32; ww = 32; }
    else               { base = 5120; hh = 16; ww = 16; }
    int tl = t - base;
    int rr = tl / ww, cc = tl % ww;

    const float* in = hin + ((size_t)b * LQ + base) * HID + ch;
    float acc = dwb[ch];
    #pragma unroll
    for (int ky = 0; ky < 3; ky++) {
        int y = rr + ky - 1;
        if (y < 0 || y >= hh) continue;
        #pragma unroll
        for (int kx = 0; kx < 3; kx++) {
            int x = cc + kx - 1;
            if (x < 0 || x >= ww) continue;
            acc += in[(size_t)(y * ww + x) * HID] * dww[(ky * 3 + kx) * HID + ch];
        }
    }
    float ge = 0.5f * acc * (1.f + erff(acc * 0.70710678118654752440f));
    hout[gid] = __float2bfloat16(ge);
}

// ---------------- host launcher ----------------
extern "C" void kernel_launch(void* const* d_in, const int* in_sizes, int n_in,
                              void* d_out, int out_size)
{
    const float* query  = (const float*)d_in[0];
    const float* refp   = (const float*)d_in[1];
    const float* feat   = (const float*)d_in[2];
    const float* qn_g   = (const float*)d_in[5];
    const float* qn_b   = (const float*)d_in[6];
    const float* fn_g   = (const float*)d_in[7];
    const float* fn_b   = (const float*)d_in[8];
    const float* W_off  = (const float*)d_in[9];
    const float* b_off  = (const float*)d_in[10];
    const float* W_attn = (const float*)d_in[11];
    const float* b_attn = (const float*)d_in[12];
    const float* W_val  = (const float*)d_in[13];
    const float* b_val  = (const float*)d_in[14];
    const float* W_out  = (const float*)d_in[15];
    const float* b_out  = (const float*)d_in[16];
    const float* ffn_g  = (const float*)d_in[17];
    const float* ffn_b  = (const float*)d_in[18];
    const float* fc1_w  = (const float*)d_in[19];
    const float* fc1_b  = (const float*)d_in[20];
    const float* dw_w   = (const float*)d_in[21];
    const float* dw_b   = (const float*)d_in[22];
    const float* fc2_w  = (const float*)d_in[23];
    const float* fc2_b  = (const float*)d_in[24];
    float* out = (float*)d_out;

    float *pv, *poa, *ph1, *pbproj;
    __nv_bfloat16 *plnq, *plnf, *plnx, *pattnb, *ph2b;
    __nv_bfloat16 *pwval, *pwout, *pwproj, *pwfc1, *pwfc2;
    cudaGetSymbolAddress((void**)&pv,     g_v);
    cudaGetSymbolAddress((void**)&poa,    g_oa);
    cudaGetSymbolAddress((void**)&ph1,    g_h1);
    cudaGetSymbolAddress((void**)&pbproj, g_bproj);
    cudaGetSymbolAddress((void**)&plnq,   g_lnq);
    cudaGetSymbolAddress((void**)&plnf,   g_lnf);
    cudaGetSymbolAddress((void**)&plnx,   g_lnx);
    cudaGetSymbolAddress((void**)&pattnb, g_attnb);
    cudaGetSymbolAddress((void**)&ph2b,   g_h2b);
    cudaGetSymbolAddress((void**)&pwval,  g_wval);
    cudaGetSymbolAddress((void**)&pwout,  g_wout);
    cudaGetSymbolAddress((void**)&pwproj, g_wproj);
    cudaGetSymbolAddress((void**)&pwfc1,  g_wfc1);
    cudaGetSymbolAddress((void**)&pwfc2,  g_wfc2);

    // LN + bf16 casts
    ln_cast<<<NTOK, 256>>>(query, qn_g, qn_b, plnq);
    ln_cast<<<NFEAT, 256>>>(feat, fn_g, fn_b, plnf);

    // weight transpose-casts
    tcast<<<(DIM * DV + 255) / 256, 256>>>(W_val, pwval, DIM, DV);
    tcast<<<(DV * DIM + 255) / 256, 256>>>(W_out, pwout, DV, DIM);
    tcast<<<(DIM * HID + 255) / 256, 256>>>(fc1_w, pwfc1, DIM, HID);
    tcast<<<(HID * DIM + 255) / 256, 256>>>(fc2_w, pwfc2, HID, DIM);
    build_proj<<<(OA_LD * DIM + 255) / 256, 256>>>(W_off, W_attn, b_off, b_attn,
                                                   pwproj, pbproj);

    // v = LN(feat) @ W_val + b_val           (8192 x 384, K=768)
    gemm_mma<false, false><<<dim3(DV / BN, NFEAT / BM), 256>>>(
        plnf, pwval, b_val, nullptr, pv, NFEAT, DV, DIM);

    // oa = LN(q) @ [W_off|W_attn|pad] + b    (43008 x 96, K=768)
    gemm_mma<false, false><<<dim3(OA_LD / BN, NTOK / BM), 256>>>(
        plnq, pwproj, pbproj, nullptr, poa, NTOK, OA_LD, DIM);

    // softmax + bilinear gather -> attn (bf16)
    sample_kernel<<<NTOK, 192>>>(poa, refp, pattnb);

    // x = attn @ W_out + b_out + query       (43008 x 768, K=384)
    gemm_mma<true, false><<<dim3(DIM / BN, NTOK / BM), 256>>>(
        pattnb, pwout, b_out, query, out, NTOK, DIM, DV);

    // FFN
    ln_cast<<<NTOK, 256>>>(out, ffn_g, ffn_b, plnx);

    // h1 = LN(x) @ fc1_w + fc1_b             (43008 x 192, K=768)
    gemm_mma<false, false><<<dim3(HID / BN, NTOK / BM), 256>>>(
        plnx, pwfc1, fc1_b, nullptr, ph1, NTOK, HID, DIM);

    // depthwise conv + gelu -> bf16
    dwconv_gelu<<<(NTOK * HID) / 256, 256>>>(ph1, dw_w, dw_b, ph2b);

    // out += h2 @ fc2_w + fc2_b              (43008 x 768, K=192)
    gemm_mma<false, true><<<dim3(DIM / BN, NTOK / BM), 256>>>(
        ph2b, pwfc2, fc2_b, nullptr, out, NTOK, DIM, HID);
}